// round 2
// baseline (speedup 1.0000x reference)
#include <cuda_runtime.h>
#include <cuda_bf16.h>
#include <cstddef>

#define HW 16384
#define SCALE 0.17677669529663689f
#define EPSBN 1e-5f

// ---------------- scratch ----------------
__device__ float g_y1[2 * 256 * HW];
__device__ float g_q [2 * 256 * HW];
__device__ float g_kv[2 * 512 * HW];
__device__ float g_y2[2 * 256 * HW];

// ---------------- GEMM: Out[o,p] = sum_c W[o,c] * X[c,p], per batch z ----------------
// 128x128 tile, 256 threads, 8x8 accum, double-buffered k=8 slabs.
// MODE 0: plain   MODE 1: relu(bn(.))   MODE 2: relu(resid + gamma*relu(bn(.)))
template<int MODE>
__global__ __launch_bounds__(256) void gemm_conv(
    const float* __restrict__ X, const float* __restrict__ Wm, float* __restrict__ Out,
    const float* __restrict__ bw, const float* __restrict__ bb,
    const float* __restrict__ bm, const float* __restrict__ bv,
    const float* __restrict__ gamma, const float* __restrict__ resid)
{
    __shared__ float Ws[2][8][128];
    __shared__ float Xs[2][8][128];

    const int tid = threadIdx.x;
    const int p0 = blockIdx.x * 128;
    const int o0 = blockIdx.y * 128;
    const int z  = blockIdx.z;
    const float* Xb = X + (size_t)z * 256 * HW;

    const int tx = tid & 15, ty = tid >> 4;

    const int wrow = tid >> 1;          // 0..127
    const int wc4  = (tid & 1) * 4;     // 0 or 4
    const int xrow = tid >> 5;          // 0..7
    const int xcol = (tid & 31) * 4;    // 0..124

    float acc[8][8];
#pragma unroll
    for (int ii = 0; ii < 8; ii++)
#pragma unroll
        for (int jj = 0; jj < 8; jj++) acc[ii][jj] = 0.f;

    // prime buffer 0
    float4 wreg = *(const float4*)&Wm[(o0 + wrow) * 256 + wc4];
    float4 xreg = *(const float4*)&Xb[(size_t)xrow * HW + p0 + xcol];
    Ws[0][wc4 + 0][wrow] = wreg.x;
    Ws[0][wc4 + 1][wrow] = wreg.y;
    Ws[0][wc4 + 2][wrow] = wreg.z;
    Ws[0][wc4 + 3][wrow] = wreg.w;
    *(float4*)&Xs[0][xrow][xcol] = xreg;
    __syncthreads();

    for (int kt = 0; kt < 32; kt++) {
        const int cur = kt & 1;
        float4 wn, xn;
        if (kt < 31) {
            wn = *(const float4*)&Wm[(o0 + wrow) * 256 + (kt + 1) * 8 + wc4];
            xn = *(const float4*)&Xb[(size_t)((kt + 1) * 8 + xrow) * HW + p0 + xcol];
        }
#pragma unroll
        for (int kk = 0; kk < 8; kk++) {
            float4 a0 = *(float4*)&Ws[cur][kk][ty * 8];
            float4 a1 = *(float4*)&Ws[cur][kk][ty * 8 + 4];
            float4 b0 = *(float4*)&Xs[cur][kk][tx * 8];
            float4 b1 = *(float4*)&Xs[cur][kk][tx * 8 + 4];
            float a[8] = {a0.x, a0.y, a0.z, a0.w, a1.x, a1.y, a1.z, a1.w};
            float b[8] = {b0.x, b0.y, b0.z, b0.w, b1.x, b1.y, b1.z, b1.w};
#pragma unroll
            for (int ii = 0; ii < 8; ii++)
#pragma unroll
                for (int jj = 0; jj < 8; jj++)
                    acc[ii][jj] = fmaf(a[ii], b[jj], acc[ii][jj]);
        }
        if (kt < 31) {
            const int nxt = cur ^ 1;
            Ws[nxt][wc4 + 0][wrow] = wn.x;
            Ws[nxt][wc4 + 1][wrow] = wn.y;
            Ws[nxt][wc4 + 2][wrow] = wn.z;
            Ws[nxt][wc4 + 3][wrow] = wn.w;
            *(float4*)&Xs[nxt][xrow][xcol] = xn;
            __syncthreads();
        }
    }

    const int Mtot = gridDim.y * 128;
    float* Ob = Out + (size_t)z * Mtot * HW;
#pragma unroll
    for (int ii = 0; ii < 8; ii++) {
        const int o = o0 + ty * 8 + ii;
        float mul = 1.f, add = 0.f, gm = 0.f;
        if (MODE >= 1) {
            float inv = bw[o] * rsqrtf(bv[o] + EPSBN);
            mul = inv;
            add = fmaf(-bm[o], inv, bb[o]);
        }
        if (MODE == 2) gm = gamma[o];
        float* orow = &Ob[(size_t)o * HW + p0 + tx * 8];
        const float* rrow = (MODE == 2) ? &resid[((size_t)z * 256 + o) * HW + p0 + tx * 8] : nullptr;
        float outv[8];
#pragma unroll
        for (int jj = 0; jj < 8; jj++) {
            float v = acc[ii][jj];
            if (MODE >= 1) { v = fmaf(v, mul, add); v = fmaxf(v, 0.f); }
            if (MODE == 2) { v = fmaf(gm, v, rrow[jj]); v = fmaxf(v, 0.f); }
            outv[jj] = v;
        }
        *(float4*)&orow[0] = make_float4(outv[0], outv[1], outv[2], outv[3]);
        *(float4*)&orow[4] = make_float4(outv[4], outv[5], outv[6], outv[7]);
    }
}

// ---------------- Halo attention ----------------
// 256 threads: qrow = tid&63, quarter qt = tid>>6 (one 7x7 key quadrant each).
// Partial softmax states merged via smem. Epilogue fuses relu(bna(.)).
#define KS 36
// Ksm 196*36 + Vsm 196*36 + Qsm 64*32 + QH 64*27 + QW 64*27
#define ATTN_SMEM_FLOATS (7056 + 7056 + 2048 + 1728 + 1728)

__global__ __launch_bounds__(256, 2) void attn_kernel(
    const float* __restrict__ q, const float* __restrict__ kv,
    const float* __restrict__ hrel, const float* __restrict__ wrel,
    const float* __restrict__ aw, const float* __restrict__ ab,
    const float* __restrict__ am, const float* __restrict__ av,
    float* __restrict__ y2)
{
    extern __shared__ float sm[];
    float* Ksm = sm;             // 196 * 36
    float* Vsm = sm + 7056;      // 196 * 36
    float* Qsm = sm + 14112;     // 64 * 32
    float* QH  = sm + 16160;     // 64 * 27
    float* QW  = sm + 17888;     // 64 * 27

    const int blk = blockIdx.x, bh = blockIdx.y;
    const int b = bh >> 3, head = bh & 7;
    const int hb = blk >> 4, wb = blk & 15;
    const int tid = threadIdx.x;

    // ---- load Q tile (64 q-positions x 32 dims) ----
    const int qchan = b * 256 + head * 32;
    for (int idx = tid; idx < 2048; idx += 256) {
        int d = idx >> 6, qq = idx & 63;
        int ii = qq >> 3, jj = qq & 7;
        Qsm[qq * 32 + d] =
            q[((size_t)(qchan + d) << 14) + (hb * 8 + ii) * 128 + wb * 8 + jj];
    }

    // ---- gather K/V halo window (196 x 32 each), zero-padded at borders ----
    const int r0 = hb * 8 - 3, c0 = wb * 8 - 3;
    const int kvchan = b * 512 + head * 64;
    for (int e = tid; e < 196 * 64; e += 256) {
        int dd = e / 196, kp = e - dd * 196;
        int kh = kp / 14, kw = kp - kh * 14;
        int r = r0 + kh, c = c0 + kw;
        float val = 0.f;
        if ((unsigned)r < 128u && (unsigned)c < 128u)
            val = kv[((size_t)(kvchan + dd) << 14) + r * 128 + c];
        if (dd < 32) Ksm[kp * KS + dd] = val;
        else         Vsm[kp * KS + dd - 32] = val;
    }
    __syncthreads();

    // ---- per-row relative position dots (rel tables read via L1/L2) ----
    for (int idx = tid; idx < 1728; idx += 256) {
        int row = idx / 27, r = idx - row * 27;
        float s1 = 0.f, s2 = 0.f;
        const float* qr = Qsm + row * 32;
        const float* hr = hrel + r * 32;
        const float* wr = wrel + r * 32;
#pragma unroll 8
        for (int d = 0; d < 32; d++) {
            s1 = fmaf(qr[d], hr[d], s1);
            s2 = fmaf(qr[d], wr[d], s2);
        }
        QH[idx] = s1; QW[idx] = s2;
    }
    __syncthreads();

    const int qt = tid >> 6, t = tid & 63;
    const int i = t >> 3, j = t & 7;
    const int kh0 = (qt >> 1) * 7, kw0 = (qt & 1) * 7;

    float4 Qr4[8];
    const float4* qrow4 = (const float4*)(Qsm + t * 32);
#pragma unroll
    for (int u = 0; u < 8; u++) {
        float4 v = qrow4[u];
        v.x *= SCALE; v.y *= SCALE; v.z *= SCALE; v.w *= SCALE;
        Qr4[u] = v;
    }

    float m = -1e30f, l = 0.f;
    float4 acc4[8] = {};

    const float* QHrow = QH + t * 27 + 13 - i;   // index with +kh
    const float* QWrow = QW + t * 27 + 13 - j;   // index with +kw

    for (int khi = 0; khi < 7; khi++) {
        const int kh = kh0 + khi;
        float ph = QHrow[kh];
        float s[7];
        const float* Kb = Ksm + (kh * 14 + kw0) * KS;
#pragma unroll
        for (int kwi = 0; kwi < 7; kwi++) {
            const float4* K4 = (const float4*)(Kb + kwi * KS);
            float d0 = 0.f, d1 = 0.f, d2 = 0.f, d3 = 0.f;
#pragma unroll
            for (int u = 0; u < 8; u++) {
                float4 k4 = K4[u];
                d0 = fmaf(Qr4[u].x, k4.x, d0);
                d1 = fmaf(Qr4[u].y, k4.y, d1);
                d2 = fmaf(Qr4[u].z, k4.z, d2);
                d3 = fmaf(Qr4[u].w, k4.w, d3);
            }
            s[kwi] = (d0 + d1) + (d2 + d3) + ph + QWrow[kw0 + kwi];
        }
        float cmax = s[0];
#pragma unroll
        for (int kwi = 1; kwi < 7; kwi++) cmax = fmaxf(cmax, s[kwi]);
        float mn = fmaxf(m, cmax);
        float corr = __expf(m - mn);
        m = mn;
        l *= corr;
#pragma unroll
        for (int u = 0; u < 8; u++) {
            acc4[u].x *= corr; acc4[u].y *= corr; acc4[u].z *= corr; acc4[u].w *= corr;
        }
        const float* Vb = Vsm + (kh * 14 + kw0) * KS;
#pragma unroll
        for (int kwi = 0; kwi < 7; kwi++) {
            float p = __expf(s[kwi] - m);
            l += p;
            const float4* V4 = (const float4*)(Vb + kwi * KS);
#pragma unroll
            for (int u = 0; u < 8; u++) {
                float4 v4 = V4[u];
                acc4[u].x = fmaf(p, v4.x, acc4[u].x);
                acc4[u].y = fmaf(p, v4.y, acc4[u].y);
                acc4[u].z = fmaf(p, v4.z, acc4[u].z);
                acc4[u].w = fmaf(p, v4.w, acc4[u].w);
            }
        }
    }

    // ---- merge 4 quarter-partials (reuse Ksm: 192 rows * 36 floats) ----
    __syncthreads();
    float* mb = Ksm;
    if (qt > 0) {
        float* row = mb + ((qt - 1) * 64 + t) * KS;
        float4* row4 = (float4*)row;
#pragma unroll
        for (int u = 0; u < 8; u++) row4[u] = acc4[u];
        row[32] = m;
        row[33] = l;
    }
    __syncthreads();
    if (qt == 0) {
#pragma unroll
        for (int p = 0; p < 3; p++) {
            const float* row = mb + (p * 64 + t) * KS;
            float m2 = row[32], l2 = row[33];
            float mn = fmaxf(m, m2);
            float c1 = __expf(m - mn), c2 = __expf(m2 - mn);
            m = mn;
            l = l * c1 + l2 * c2;
            const float4* row4 = (const float4*)row;
#pragma unroll
            for (int u = 0; u < 8; u++) {
                float4 o4 = row4[u];
                acc4[u].x = acc4[u].x * c1 + o4.x * c2;
                acc4[u].y = acc4[u].y * c1 + o4.y * c2;
                acc4[u].z = acc4[u].z * c1 + o4.z * c2;
                acc4[u].w = acc4[u].w * c1 + o4.w * c2;
            }
        }
        float invl = 1.f / l;
        size_t obase = ((size_t)(b * 256 + head * 32) << 14) + (hb * 8 + i) * 128 + wb * 8 + j;
#pragma unroll
        for (int u = 0; u < 8; u++) {
            float vals[4] = {acc4[u].x, acc4[u].y, acc4[u].z, acc4[u].w};
#pragma unroll
            for (int cc = 0; cc < 4; cc++) {
                int d = u * 4 + cc;
                int ch = head * 32 + d;
                float inv  = aw[ch] * rsqrtf(av[ch] + EPSBN);
                float bias = fmaf(-am[ch], inv, ab[ch]);
                float v = fmaf(vals[cc] * invl, inv, bias);
                v = fmaxf(v, 0.f);
                y2[obase + ((size_t)d << 14)] = v;
            }
        }
    }
}

// ---------------- launch ----------------
extern "C" void kernel_launch(void* const* d_in, const int* in_sizes, int n_in,
                              void* d_out, int out_size)
{
    const float* x     = (const float*)d_in[0];
    const float* w1    = (const float*)d_in[1];
    const float* qw    = (const float*)d_in[2];
    const float* kvw   = (const float*)d_in[3];
    const float* w3    = (const float*)d_in[4];
    const float* hrel  = (const float*)d_in[5];
    const float* wrel  = (const float*)d_in[6];
    const float* bn1w  = (const float*)d_in[7];
    const float* bn1b  = (const float*)d_in[8];
    const float* bn1m  = (const float*)d_in[9];
    const float* bn1v  = (const float*)d_in[10];
    const float* bnaw  = (const float*)d_in[11];
    const float* bnab  = (const float*)d_in[12];
    const float* bnam  = (const float*)d_in[13];
    const float* bnav  = (const float*)d_in[14];
    const float* bn3w  = (const float*)d_in[15];
    const float* bn3b  = (const float*)d_in[16];
    const float* bn3m  = (const float*)d_in[17];
    const float* bn3v  = (const float*)d_in[18];
    const float* gamma = (const float*)d_in[19];
    float* out = (float*)d_out;

    float *p_y1, *p_q, *p_kv, *p_y2;
    cudaGetSymbolAddress((void**)&p_y1, g_y1);
    cudaGetSymbolAddress((void**)&p_q,  g_q);
    cudaGetSymbolAddress((void**)&p_kv, g_kv);
    cudaGetSymbolAddress((void**)&p_y2, g_y2);

    const int attn_smem = ATTN_SMEM_FLOATS * 4;
    cudaFuncSetAttribute(attn_kernel, cudaFuncAttributeMaxDynamicSharedMemorySize, attn_smem);

    dim3 blk(256);
    // 1) y1 = relu(bn1(w1 @ x))
    gemm_conv<1><<<dim3(128, 2, 2), blk>>>(x, w1, p_y1,
                                           bn1w, bn1b, bn1m, bn1v, nullptr, nullptr);
    // 2) q = q_w @ y1
    gemm_conv<0><<<dim3(128, 2, 2), blk>>>(p_y1, qw, p_q,
                                           nullptr, nullptr, nullptr, nullptr, nullptr, nullptr);
    // 3) kv = kv_w @ y1
    gemm_conv<0><<<dim3(128, 4, 2), blk>>>(p_y1, kvw, p_kv,
                                           nullptr, nullptr, nullptr, nullptr, nullptr, nullptr);
    // 4) attention + fused relu(bna(.))
    attn_kernel<<<dim3(256, 16), 256, attn_smem>>>(p_q, p_kv, hrel, wrel,
                                                   bnaw, bnab, bnam, bnav, p_y2);
    // 5) out = relu(x + gamma*relu(bn3(w3 @ y2)))
    gemm_conv<2><<<dim3(128, 2, 2), blk>>>(p_y2, w3, out,
                                           bn3w, bn3b, bn3m, bn3v, gamma, x);
}